// round 4
// baseline (speedup 1.0000x reference)
#include <cuda_runtime.h>

#define Bb 4
#define Cc 64
#define Nn 8192
#define Kk 16
#define Dd 64
#define S_CHUNK 4
#define CHUNK_N (Nn / S_CHUNK)

typedef unsigned long long ull;

// ---------------- scratch (static __device__, no allocations) ----------------
__device__ __align__(16) float g_xT[Bb * Nn * Cc];       // x transposed: (B, N, C)
__device__ float g_sq[Bb * Nn];                          // squared norms of pos
__device__ int   g_idx[Bb * Nn * Kk];                    // knn indices
__device__ __align__(16) ull g_pk[(size_t)Bb * Nn * S_CHUNK * 16]; // partial sorted keys
__device__ __align__(16) float g_WsumNeg[Cc * Dd];       // -sum_k W[k,c,d]
__device__ float g_partial[(Bb * Nn / 64) * 2 * Dd];     // per-block BN partials (sum, sumsq)
__device__ float g_scale[Dd], g_shift[Dd];

// ---------------- f32x2 helpers ---------------------------------------------
#define FMA2(d, a, b) asm("fma.rn.f32x2 %0, %1, %2, %0;" : "+l"(d) : "l"(a), "l"(b))
__device__ __forceinline__ ull pack2(float x) {
    ull r;
    asm("mov.b64 %0, {%1, %1};" : "=l"(r) : "r"(__float_as_uint(x)));
    return r;
}
__device__ __forceinline__ void unpack2(ull v, float& lo, float& hi) {
    unsigned a, b;
    asm("mov.b64 {%0, %1}, %2;" : "=r"(a), "=r"(b) : "l"(v));
    lo = __uint_as_float(a); hi = __uint_as_float(b);
}

// ---------------- prep: squared norms of pos --------------------------------
// Match XLA reduce lowering exactly: ((x*x + y*y) + z*z), no fma contraction.
__global__ void prep_sq(const float* __restrict__ pos) {
    int b = blockIdx.y;
    int n = blockIdx.x * 256 + threadIdx.x;
    const float* pb = pos + b * 3 * Nn;
    float x = pb[n], y = pb[Nn + n], z = pb[2 * Nn + n];
    float s = __fadd_rn(__fadd_rn(__fmul_rn(x, x), __fmul_rn(y, y)), __fmul_rn(z, z));
    g_sq[b * Nn + n] = s;
}

// ---------------- prep: transpose x (B,C,N) -> xT (B,N,C) -------------------
__global__ void prep_xT(const float* __restrict__ x) {
    __shared__ float t[32][33];
    int b = blockIdx.z;
    int n0 = blockIdx.x * 32, c0 = blockIdx.y * 32;
    int tx = threadIdx.x, ty = threadIdx.y;
#pragma unroll
    for (int i = 0; i < 4; ++i)
        t[ty + 8 * i][tx] = x[(size_t)b * Cc * Nn + (size_t)(c0 + ty + 8 * i) * Nn + n0 + tx];
    __syncthreads();
#pragma unroll
    for (int i = 0; i < 4; ++i)
        g_xT[(size_t)b * Nn * Cc + (size_t)(n0 + ty + 8 * i) * Cc + c0 + tx] = t[tx][ty + 8 * i];
}

// ---------------- prep: negated filter k-sum --------------------------------
__global__ void prep_wsum(const float* __restrict__ filt) {
    int i = blockIdx.x * 256 + threadIdx.x;  // 0..4095 = c*64+d
    float s = 0.f;
#pragma unroll
    for (int k = 0; k < Kk; ++k) s += filt[k * Cc * Dd + i];
    g_WsumNeg[i] = -s;
}

// ---------------- KNN partial: top-16 within a 2048-candidate chunk ---------
// Key: (sortable(dn) << 32) | ~idx  -> total order == top_k (value desc, idx asc).
// Keys are UNIQUE, so insertion order is irrelevant and replace-min-by-
// equality-scan is exact.
__device__ __forceinline__ ull knn_key(float dn, int j) {
    int bi = __float_as_int(dn);
    unsigned u = (unsigned)(bi ^ ((bi >> 31) | 0x80000000));
    return ((ull)u << 32) | (unsigned)(~j);
}
__device__ __forceinline__ ull um64(ull a, ull b) { return a < b ? a : b; }

#define BUFCAP 12

__global__ void __launch_bounds__(128) knn_partial(const float* __restrict__ pos) {
    __shared__ __align__(16) float4 tile[CHUNK_N];
    __shared__ ull sbuf[BUFCAP][128];
    int b = blockIdx.z;
    int chunk = blockIdx.y;
    int c0 = chunk * CHUNK_N;
    int tid = threadIdx.x;
    int n = blockIdx.x * 128 + tid;
    const float* pb = pos + b * 3 * Nn;
    float qx = pb[n], qy = pb[Nn + n], qz = pb[2 * Nn + n];
    float qs = g_sq[b * Nn + n];

    for (int i = tid; i < CHUNK_N; i += 128) {
        int j = c0 + i;
        tile[i] = make_float4(pb[j], pb[Nn + j], pb[2 * Nn + j], g_sq[b * Nn + j]);
    }

    // sentinel keys: decode below any real key, distinct
    ull kl[16];
#pragma unroll
    for (int t = 0; t < 16; ++t) kl[t] = (0x007FFFFFull << 32) | (unsigned)t;
    ull kmin = kl[0];
    float vminf = __int_as_float(0xFF800000);  // -inf
    int cnt = 0;
    __syncthreads();

    for (int jb = 0; jb < CHUNK_N; jb += 4) {
        float4 p0 = tile[jb + 0], p1 = tile[jb + 1], p2 = tile[jb + 2], p3 = tile[jb + 3];
        float d0 = __fadd_rn(__fmaf_rn(2.0f, __fmaf_rn(qz, p0.z, __fmaf_rn(qy, p0.y, __fmul_rn(qx, p0.x))), -qs), -p0.w);
        float d1 = __fadd_rn(__fmaf_rn(2.0f, __fmaf_rn(qz, p1.z, __fmaf_rn(qy, p1.y, __fmul_rn(qx, p1.x))), -qs), -p1.w);
        float d2 = __fadd_rn(__fmaf_rn(2.0f, __fmaf_rn(qz, p2.z, __fmaf_rn(qy, p2.y, __fmul_rn(qx, p2.x))), -qs), -p2.w);
        float d3 = __fadd_rn(__fmaf_rn(2.0f, __fmaf_rn(qz, p3.z, __fmaf_rn(qy, p3.y, __fmul_rn(qx, p3.x))), -qs), -p3.w);
        bool q0 = d0 >= vminf, q1 = d1 >= vminf, q2 = d2 >= vminf, q3 = d3 >= vminf;
        if (q0 | q1 | q2 | q3) {
            int jg = c0 + jb;
            if (q0) { sbuf[cnt][tid] = knn_key(d0, jg + 0); cnt++; }
            if (q1) { sbuf[cnt][tid] = knn_key(d1, jg + 1); cnt++; }
            if (q2) { sbuf[cnt][tid] = knn_key(d2, jg + 2); cnt++; }
            if (q3) { sbuf[cnt][tid] = knn_key(d3, jg + 3); cnt++; }
        }
        if (__any_sync(0xFFFFFFFFu, cnt > 8)) {
            int mx = (int)__reduce_max_sync(0xFFFFFFFFu, (unsigned)cnt);
            for (int m = 0; m < mx; ++m) {
                ull kc = sbuf[m][tid];
                bool take = (m < cnt) && (kc > kmin);
                ull km = kmin;
#pragma unroll
                for (int t = 0; t < 16; ++t) kl[t] = (take && kl[t] == km) ? kc : kl[t];
                ull a0 = um64(kl[0], kl[1]), a1 = um64(kl[2], kl[3]);
                ull a2 = um64(kl[4], kl[5]), a3 = um64(kl[6], kl[7]);
                ull a4 = um64(kl[8], kl[9]), a5 = um64(kl[10], kl[11]);
                ull a6 = um64(kl[12], kl[13]), a7 = um64(kl[14], kl[15]);
                a0 = um64(a0, a1); a2 = um64(a2, a3); a4 = um64(a4, a5); a6 = um64(a6, a7);
                kmin = um64(um64(a0, a2), um64(a4, a6));
            }
            cnt = 0;
            unsigned u = (unsigned)(kmin >> 32);
            unsigned tb = (u & 0x80000000u) ? (u ^ 0x80000000u) : ~u;
            vminf = __int_as_float((int)tb);
        }
    }
    // final compaction
    {
        int mx = (int)__reduce_max_sync(0xFFFFFFFFu, (unsigned)cnt);
        for (int m = 0; m < mx; ++m) {
            ull kc = sbuf[m][tid];
            bool take = (m < cnt) && (kc > kmin);
            ull km = kmin;
#pragma unroll
            for (int t = 0; t < 16; ++t) kl[t] = (take && kl[t] == km) ? kc : kl[t];
            ull a0 = um64(kl[0], kl[1]), a1 = um64(kl[2], kl[3]);
            ull a2 = um64(kl[4], kl[5]), a3 = um64(kl[6], kl[7]);
            ull a4 = um64(kl[8], kl[9]), a5 = um64(kl[10], kl[11]);
            ull a6 = um64(kl[12], kl[13]), a7 = um64(kl[14], kl[15]);
            a0 = um64(a0, a1); a2 = um64(a2, a3); a4 = um64(a4, a5); a6 = um64(a6, a7);
            kmin = um64(um64(a0, a2), um64(a4, a6));
        }
    }
    // sort 16 keys descending (odd-even transposition, static indexing)
#pragma unroll
    for (int pass = 0; pass < 16; ++pass) {
#pragma unroll
        for (int t = (pass & 1); t < 15; t += 2) {
            ull lo = um64(kl[t], kl[t + 1]);
            ull hi = (kl[t] < kl[t + 1]) ? kl[t + 1] : kl[t];
            kl[t] = hi; kl[t + 1] = lo;
        }
    }
    ull* outp = g_pk + (((size_t)b * Nn + n) * S_CHUNK + chunk) * 16;
#pragma unroll
    for (int t = 0; t < 16; ++t) outp[t] = kl[t];
}

// ---------------- KNN merge: 4-way merge of sorted chunk lists --------------
__global__ void knn_merge() {
    int q = blockIdx.x * 128 + threadIdx.x;  // 0 .. Bb*Nn-1
    const ull* base = g_pk + (size_t)q * (S_CHUNK * 16);
    ull h0 = base[0], h1 = base[16], h2 = base[32], h3 = base[48];
    int i0 = 0, i1 = 0, i2 = 0, i3 = 0;
    int* op = g_idx + (size_t)q * 16;
#pragma unroll
    for (int t = 0; t < 16; ++t) {
        ull best = h0; int s = 0;
        if (h1 > best) { best = h1; s = 1; }
        if (h2 > best) { best = h2; s = 2; }
        if (h3 > best) { best = h3; s = 3; }
        op[t] = (int)(~(unsigned)best);
        if (s == 0)      { ++i0; h0 = (i0 < 16) ? base[i0]      : 0ull; }
        else if (s == 1) { ++i1; h1 = (i1 < 16) ? base[16 + i1] : 0ull; }
        else if (s == 2) { ++i2; h2 = (i2 < 16) ? base[32 + i2] : 0ull; }
        else             { ++i3; h3 = (i3 < 16) ? base[48 + i3] : 0ull; }
    }
}

// ---------------- fused gather + spectral GEMM + BN partials ----------------
// 17 reduction stages: k=0..15 neighbors w/ filter_k; k=16 self w/ -sum_k W.
// Inner product uses packed f32x2 FMA (identical per-lane rounding).
__global__ void gconv_kernel(const float* __restrict__ filt, float* __restrict__ out) {
    __shared__ __align__(16) float Esm[64 * 64];  // [c][p]
    __shared__ __align__(16) float Wsm[64 * 64];  // [c][d]
    int b = blockIdx.y;
    int n0 = blockIdx.x * 64;
    int tid = threadIdx.x;
    int tx = tid & 15, ty = tid >> 4;         // d-quad, p-quad
    int p = tid & 63, cg = tid >> 6;          // staging roles

    ull acc2[4][2];
#pragma unroll
    for (int i = 0; i < 4; ++i) { acc2[i][0] = 0ull; acc2[i][1] = 0ull; }

    const float* xTb = g_xT + (size_t)b * Nn * Cc;

    for (int kk = 0; kk <= Kk; ++kk) {
        const float* Wsrc = (kk < Kk) ? (filt + kk * Cc * Dd) : g_WsumNeg;
#pragma unroll
        for (int i = 0; i < 4; ++i)
            ((float4*)Wsm)[tid + 256 * i] = ((const float4*)Wsrc)[tid + 256 * i];
        int m = (kk < Kk) ? g_idx[((size_t)b * Nn + n0 + p) * Kk + kk] : (n0 + p);
        const float* row = xTb + (size_t)m * Cc + cg * 16;
#pragma unroll
        for (int i = 0; i < 4; ++i) {
            float4 vv = ((const float4*)row)[i];
            int c = cg * 16 + i * 4;
            Esm[(c + 0) * 64 + p] = vv.x;
            Esm[(c + 1) * 64 + p] = vv.y;
            Esm[(c + 2) * 64 + p] = vv.z;
            Esm[(c + 3) * 64 + p] = vv.w;
        }
        __syncthreads();
#pragma unroll 8
        for (int c = 0; c < 64; ++c) {
            float4 e = *(const float4*)&Esm[c * 64 + ty * 4];
            ull w01 = *(const ull*)&Wsm[c * 64 + tx * 4];
            ull w23 = *(const ull*)&Wsm[c * 64 + tx * 4 + 2];
            ull ex = pack2(e.x), ey = pack2(e.y), ez = pack2(e.z), ew = pack2(e.w);
            FMA2(acc2[0][0], ex, w01); FMA2(acc2[0][1], ex, w23);
            FMA2(acc2[1][0], ey, w01); FMA2(acc2[1][1], ey, w23);
            FMA2(acc2[2][0], ez, w01); FMA2(acc2[2][1], ez, w23);
            FMA2(acc2[3][0], ew, w01); FMA2(acc2[3][1], ew, w23);
        }
        __syncthreads();
    }

    float acc[4][4];
#pragma unroll
    for (int i = 0; i < 4; ++i) {
        unpack2(acc2[i][0], acc[i][0], acc[i][1]);
        unpack2(acc2[i][1], acc[i][2], acc[i][3]);
    }

    float psum[4], psq[4];
#pragma unroll
    for (int j = 0; j < 4; ++j) {
        psum[j] = acc[0][j] + acc[1][j] + acc[2][j] + acc[3][j];
        psq[j] = acc[0][j] * acc[0][j] + acc[1][j] * acc[1][j] +
                 acc[2][j] * acc[2][j] + acc[3][j] * acc[3][j];
    }
#pragma unroll
    for (int i = 0; i < 4; ++i)
#pragma unroll
        for (int j = 0; j < 4; ++j)
            Esm[(tx * 4 + j) * 64 + (ty * 4 + i)] = acc[i][j];
#pragma unroll
    for (int j = 0; j < 4; ++j) Wsm[ty * 64 + tx * 4 + j] = psum[j];
    __syncthreads();

    {
        int d = tid >> 2, seg = tid & 3;
        float4* orow = (float4*)(out + (size_t)b * Dd * Nn + (size_t)d * Nn + n0);
        const float4* trow = (const float4*)&Esm[d * 64];
#pragma unroll
        for (int qq = 0; qq < 4; ++qq) orow[seg * 4 + qq] = trow[seg * 4 + qq];
    }
    int blk = b * gridDim.x + blockIdx.x;
    if (tid < 64) {
        float s = 0.f;
#pragma unroll
        for (int t = 0; t < 16; ++t) s += Wsm[t * 64 + tid];
        g_partial[blk * 128 + tid] = s;
    }
    __syncthreads();
#pragma unroll
    for (int j = 0; j < 4; ++j) Wsm[ty * 64 + tx * 4 + j] = psq[j];
    __syncthreads();
    if (tid < 64) {
        float s = 0.f;
#pragma unroll
        for (int t = 0; t < 16; ++t) s += Wsm[t * 64 + tid];
        g_partial[blk * 128 + 64 + tid] = s;
    }
}

// ---------------- finalize BN stats (deterministic) -------------------------
__global__ void finalize_kernel(const float* __restrict__ gamma, const float* __restrict__ beta) {
    int d = threadIdx.x;  // 64 threads
    float s = 0.f, s2 = 0.f;
    const int nblk = Bb * Nn / 64;
#pragma unroll 8
    for (int blk = 0; blk < nblk; ++blk) {
        s += g_partial[blk * 128 + d];
        s2 += g_partial[blk * 128 + 64 + d];
    }
    const float inv = 1.0f / (float)(Bb * Nn);
    float mean = s * inv;
    float var = s2 * inv - mean * mean;
    float sc = gamma[d] * rsqrtf(var + 1e-5f);
    g_scale[d] = sc;
    g_shift[d] = beta[d] - mean * sc;
}

// ---------------- apply BN in place on d_out --------------------------------
__global__ void bn_apply(float* __restrict__ out) {
    int i = blockIdx.x * 256 + threadIdx.x;
    float4 v = ((float4*)out)[i];
    int d = (i >> 11) & 63;
    float sc = g_scale[d], sh = g_shift[d];
    v.x = fmaf(v.x, sc, sh);
    v.y = fmaf(v.y, sc, sh);
    v.z = fmaf(v.z, sc, sh);
    v.w = fmaf(v.w, sc, sh);
    ((float4*)out)[i] = v;
}

// ---------------- launch ----------------------------------------------------
extern "C" void kernel_launch(void* const* d_in, const int* in_sizes, int n_in,
                              void* d_out, int out_size) {
    const float* x = (const float*)d_in[0];
    const float* pos = (const float*)d_in[1];
    const float* filt = (const float*)d_in[2];
    const float* gamma = (const float*)d_in[3];
    const float* beta = (const float*)d_in[4];
    float* out = (float*)d_out;

    prep_sq<<<dim3(Nn / 256, Bb), 256>>>(pos);
    prep_xT<<<dim3(Nn / 32, Cc / 32, Bb), dim3(32, 8)>>>(x);
    prep_wsum<<<(Cc * Dd) / 256, 256>>>(filt);
    knn_partial<<<dim3(Nn / 128, S_CHUNK, Bb), 128>>>(pos);
    knn_merge<<<(Bb * Nn) / 128, 128>>>();
    gconv_kernel<<<dim3(Nn / 64, Bb), 256>>>(filt, out);
    finalize_kernel<<<1, 64>>>(gamma, beta);
    bn_apply<<<(Bb * Dd * Nn / 4) / 256, 256>>>(out);
}

// round 5
// speedup vs baseline: 1.2818x; 1.2818x over previous
#include <cuda_runtime.h>

#define Bb 4
#define Cc 64
#define Nn 8192
#define Kk 16
#define Dd 64
#define S_CHUNK 2
#define CHUNK_N (Nn / S_CHUNK)

typedef unsigned long long ull;

// ---------------- scratch (static __device__, no allocations) ----------------
__device__ __align__(16) float g_xT[Bb * Nn * Cc];       // x transposed: (B, N, C)
__device__ float g_sq[Bb * Nn];                          // squared norms of pos
__device__ int   g_idx[Bb * Nn * Kk];                    // knn indices
__device__ __align__(16) ull g_pk[(size_t)Bb * Nn * S_CHUNK * 16]; // partial sorted keys
__device__ __align__(16) float g_WsumNeg[Cc * Dd];       // -sum_k W[k,c,d]
__device__ float g_partial[(Bb * Nn / 64) * 2 * Dd];     // per-block BN partials (sum, sumsq)
__device__ float g_scale[Dd], g_shift[Dd];

// ---------------- f32x2 helpers ---------------------------------------------
#define FMA2(d, a, b) asm("fma.rn.f32x2 %0, %1, %2, %0;" : "+l"(d) : "l"(a), "l"(b))
__device__ __forceinline__ ull pack2(float x) {
    ull r;
    asm("mov.b64 %0, {%1, %1};" : "=l"(r) : "r"(__float_as_uint(x)));
    return r;
}
__device__ __forceinline__ void unpack2(ull v, float& lo, float& hi) {
    unsigned a, b;
    asm("mov.b64 {%0, %1}, %2;" : "=r"(a), "=r"(b) : "l"(v));
    lo = __uint_as_float(a); hi = __uint_as_float(b);
}

// ---------------- prep: squared norms of pos --------------------------------
// Match XLA reduce lowering exactly: ((x*x + y*y) + z*z), no fma contraction.
__global__ void prep_sq(const float* __restrict__ pos) {
    int b = blockIdx.y;
    int n = blockIdx.x * 256 + threadIdx.x;
    const float* pb = pos + b * 3 * Nn;
    float x = pb[n], y = pb[Nn + n], z = pb[2 * Nn + n];
    float s = __fadd_rn(__fadd_rn(__fmul_rn(x, x), __fmul_rn(y, y)), __fmul_rn(z, z));
    g_sq[b * Nn + n] = s;
}

// ---------------- prep: transpose x (B,C,N) -> xT (B,N,C) -------------------
__global__ void prep_xT(const float* __restrict__ x) {
    __shared__ float t[32][33];
    int b = blockIdx.z;
    int n0 = blockIdx.x * 32, c0 = blockIdx.y * 32;
    int tx = threadIdx.x, ty = threadIdx.y;
#pragma unroll
    for (int i = 0; i < 4; ++i)
        t[ty + 8 * i][tx] = x[(size_t)b * Cc * Nn + (size_t)(c0 + ty + 8 * i) * Nn + n0 + tx];
    __syncthreads();
#pragma unroll
    for (int i = 0; i < 4; ++i)
        g_xT[(size_t)b * Nn * Cc + (size_t)(n0 + ty + 8 * i) * Cc + c0 + tx] = t[tx][ty + 8 * i];
}

// ---------------- prep: negated filter k-sum --------------------------------
__global__ void prep_wsum(const float* __restrict__ filt) {
    int i = blockIdx.x * 256 + threadIdx.x;  // 0..4095 = c*64+d
    float s = 0.f;
#pragma unroll
    for (int k = 0; k < Kk; ++k) s += filt[k * Cc * Dd + i];
    g_WsumNeg[i] = -s;
}

// ---------------- KNN keys ---------------------------------------------------
// Key: (sortable(dn) << 32) | ~idx  -> total order == top_k (value desc, idx asc).
// Keys are UNIQUE (idx unique), so selection is a pure multiset top-16: any
// order-insensitive exact top-16 structure gives bit-identical results.
__device__ __forceinline__ ull knn_key(float dn, int j) {
    int bi = __float_as_int(dn);
    unsigned u = (unsigned)(bi ^ ((bi >> 31) | 0x80000000));
    return ((ull)u << 32) | (unsigned)(~j);
}
__device__ __forceinline__ float key_val(ull k) {
    unsigned u = (unsigned)(k >> 32);
    unsigned tb = (u & 0x80000000u) ? (u ^ 0x80000000u) : ~u;
    return __int_as_float((int)tb);
}

// Batched exact top-16 update: bitonic-sort the buffer (desc) then faiss-style
// merge (pair-max + bitonic cleanup). kl stays sorted descending throughout.
__device__ __forceinline__ void flush_merge(ull (&kl)[16], const ull* col, int cnt) {
    ull buf[16];
#pragma unroll
    for (int m = 0; m < 16; ++m) buf[m] = (m < cnt) ? col[m * 128] : 0ull;
    // bitonic sort, descending
#pragma unroll
    for (int k = 2; k <= 16; k <<= 1) {
#pragma unroll
        for (int j = k >> 1; j > 0; j >>= 1) {
#pragma unroll
            for (int i = 0; i < 16; ++i) {
                int l = i ^ j;
                if (l > i) {
                    bool desc = ((i & k) == 0);
                    ull a = buf[i], c = buf[l];
                    bool sw = desc ? (a < c) : (a > c);
                    buf[i] = sw ? c : a;
                    buf[l] = sw ? a : c;
                }
            }
        }
    }
    // top-16 of (kl desc) U (buf desc): pair-max then bitonic merge desc
    ull m[16];
#pragma unroll
    for (int i = 0; i < 16; ++i) { ull a = kl[i], c = buf[15 - i]; m[i] = a > c ? a : c; }
#pragma unroll
    for (int j = 8; j > 0; j >>= 1) {
#pragma unroll
        for (int i = 0; i < 16; ++i) {
            int l = i ^ j;
            if (l > i) {
                ull a = m[i], c = m[l];
                bool sw = a < c;
                m[i] = sw ? c : a;
                m[l] = sw ? a : c;
            }
        }
    }
#pragma unroll
    for (int i = 0; i < 16; ++i) kl[i] = m[i];
}

// ---------------- KNN partial: top-16 within a 4096-candidate half ----------
__global__ void __launch_bounds__(128) knn_partial(const float* __restrict__ pos) {
    __shared__ __align__(16) float4 tile[2048];
    __shared__ ull sbuf[16][128];
    int b = blockIdx.z;
    int half = blockIdx.y;
    int tid = threadIdx.x;
    int n = blockIdx.x * 128 + tid;
    const float* pb = pos + b * 3 * Nn;
    float qx = pb[n], qy = pb[Nn + n], qz = pb[2 * Nn + n];
    float qs = g_sq[b * Nn + n];

    // sentinel keys: descending, distinct; kl[15] decodes to -inf
    ull kl[16];
#pragma unroll
    for (int t = 0; t < 16; ++t) kl[t] = (0x007FFFFFull << 32) | (unsigned)(15 - t);
    float vminf = __int_as_float(0xFF800000);  // -inf
    int cnt = 0;
    ull* mycol = &sbuf[0][tid];

    for (int tt = 0; tt < CHUNK_N / 2048; ++tt) {
        int c0 = half * CHUNK_N + tt * 2048;
        __syncthreads();
        for (int i = tid; i < 2048; i += 128) {
            int j = c0 + i;
            tile[i] = make_float4(pb[j], pb[Nn + j], pb[2 * Nn + j], g_sq[b * Nn + j]);
        }
        __syncthreads();
        for (int jb = 0; jb < 2048; jb += 4) {
            float4 p0 = tile[jb + 0], p1 = tile[jb + 1], p2 = tile[jb + 2], p3 = tile[jb + 3];
            float d0 = __fadd_rn(__fmaf_rn(2.0f, __fmaf_rn(qz, p0.z, __fmaf_rn(qy, p0.y, __fmul_rn(qx, p0.x))), -qs), -p0.w);
            float d1 = __fadd_rn(__fmaf_rn(2.0f, __fmaf_rn(qz, p1.z, __fmaf_rn(qy, p1.y, __fmul_rn(qx, p1.x))), -qs), -p1.w);
            float d2 = __fadd_rn(__fmaf_rn(2.0f, __fmaf_rn(qz, p2.z, __fmaf_rn(qy, p2.y, __fmul_rn(qx, p2.x))), -qs), -p2.w);
            float d3 = __fadd_rn(__fmaf_rn(2.0f, __fmaf_rn(qz, p3.z, __fmaf_rn(qy, p3.y, __fmul_rn(qx, p3.x))), -qs), -p3.w);
            bool q0 = d0 >= vminf, q1 = d1 >= vminf, q2 = d2 >= vminf, q3 = d3 >= vminf;
            if (q0 | q1 | q2 | q3) {
                int jg = c0 + jb;
                if (q0) { mycol[cnt * 128] = knn_key(d0, jg + 0); cnt++; }
                if (q1) { mycol[cnt * 128] = knn_key(d1, jg + 1); cnt++; }
                if (q2) { mycol[cnt * 128] = knn_key(d2, jg + 2); cnt++; }
                if (q3) { mycol[cnt * 128] = knn_key(d3, jg + 3); cnt++; }
            }
            if (__any_sync(0xFFFFFFFFu, cnt > 12)) {
                flush_merge(kl, mycol, cnt);
                cnt = 0;
                vminf = key_val(kl[15]);
            }
        }
    }
    if (__any_sync(0xFFFFFFFFu, cnt > 0)) flush_merge(kl, mycol, cnt);

    ull* outp = g_pk + (((size_t)b * Nn + n) * S_CHUNK + half) * 16;
#pragma unroll
    for (int t = 0; t < 16; ++t) outp[t] = kl[t];
}

// ---------------- KNN merge: 2-way bitonic merge of sorted halves -----------
__global__ void knn_merge() {
    int q = blockIdx.x * 128 + threadIdx.x;  // 0 .. Bb*Nn-1
    const ull* base = g_pk + (size_t)q * (S_CHUNK * 16);
    ull m[16];
#pragma unroll
    for (int i = 0; i < 16; ++i) {
        ull a = base[i], c = base[16 + 15 - i];
        m[i] = a > c ? a : c;
    }
#pragma unroll
    for (int j = 8; j > 0; j >>= 1) {
#pragma unroll
        for (int i = 0; i < 16; ++i) {
            int l = i ^ j;
            if (l > i) {
                ull a = m[i], c = m[l];
                bool sw = a < c;
                m[i] = sw ? c : a;
                m[l] = sw ? a : c;
            }
        }
    }
    int* op = g_idx + (size_t)q * 16;
#pragma unroll
    for (int t = 0; t < 16; ++t) op[t] = (int)(~(unsigned)m[t]);
}

// ---------------- fused gather + spectral GEMM + BN partials ----------------
// 17 reduction stages: k=0..15 neighbors w/ filter_k; k=16 self w/ -sum_k W.
// Inner product uses packed f32x2 FMA (identical per-lane rounding).
__global__ void gconv_kernel(const float* __restrict__ filt, float* __restrict__ out) {
    __shared__ __align__(16) float Esm[64 * 64];  // [c][p]
    __shared__ __align__(16) float Wsm[64 * 64];  // [c][d]
    int b = blockIdx.y;
    int n0 = blockIdx.x * 64;
    int tid = threadIdx.x;
    int tx = tid & 15, ty = tid >> 4;         // d-quad, p-quad
    int p = tid & 63, cg = tid >> 6;          // staging roles

    ull acc2[4][2];
#pragma unroll
    for (int i = 0; i < 4; ++i) { acc2[i][0] = 0ull; acc2[i][1] = 0ull; }

    const float* xTb = g_xT + (size_t)b * Nn * Cc;

    for (int kk = 0; kk <= Kk; ++kk) {
        const float* Wsrc = (kk < Kk) ? (filt + kk * Cc * Dd) : g_WsumNeg;
#pragma unroll
        for (int i = 0; i < 4; ++i)
            ((float4*)Wsm)[tid + 256 * i] = ((const float4*)Wsrc)[tid + 256 * i];
        int m = (kk < Kk) ? g_idx[((size_t)b * Nn + n0 + p) * Kk + kk] : (n0 + p);
        const float* row = xTb + (size_t)m * Cc + cg * 16;
#pragma unroll
        for (int i = 0; i < 4; ++i) {
            float4 vv = ((const float4*)row)[i];
            int c = cg * 16 + i * 4;
            Esm[(c + 0) * 64 + p] = vv.x;
            Esm[(c + 1) * 64 + p] = vv.y;
            Esm[(c + 2) * 64 + p] = vv.z;
            Esm[(c + 3) * 64 + p] = vv.w;
        }
        __syncthreads();
#pragma unroll 8
        for (int c = 0; c < 64; ++c) {
            float4 e = *(const float4*)&Esm[c * 64 + ty * 4];
            ull w01 = *(const ull*)&Wsm[c * 64 + tx * 4];
            ull w23 = *(const ull*)&Wsm[c * 64 + tx * 4 + 2];
            ull ex = pack2(e.x), ey = pack2(e.y), ez = pack2(e.z), ew = pack2(e.w);
            FMA2(acc2[0][0], ex, w01); FMA2(acc2[0][1], ex, w23);
            FMA2(acc2[1][0], ey, w01); FMA2(acc2[1][1], ey, w23);
            FMA2(acc2[2][0], ez, w01); FMA2(acc2[2][1], ez, w23);
            FMA2(acc2[3][0], ew, w01); FMA2(acc2[3][1], ew, w23);
        }
        __syncthreads();
    }

    float acc[4][4];
#pragma unroll
    for (int i = 0; i < 4; ++i) {
        unpack2(acc2[i][0], acc[i][0], acc[i][1]);
        unpack2(acc2[i][1], acc[i][2], acc[i][3]);
    }

    float psum[4], psq[4];
#pragma unroll
    for (int j = 0; j < 4; ++j) {
        psum[j] = acc[0][j] + acc[1][j] + acc[2][j] + acc[3][j];
        psq[j] = acc[0][j] * acc[0][j] + acc[1][j] * acc[1][j] +
                 acc[2][j] * acc[2][j] + acc[3][j] * acc[3][j];
    }
#pragma unroll
    for (int i = 0; i < 4; ++i)
#pragma unroll
        for (int j = 0; j < 4; ++j)
            Esm[(tx * 4 + j) * 64 + (ty * 4 + i)] = acc[i][j];
#pragma unroll
    for (int j = 0; j < 4; ++j) Wsm[ty * 64 + tx * 4 + j] = psum[j];
    __syncthreads();

    {
        int d = tid >> 2, seg = tid & 3;
        float4* orow = (float4*)(out + (size_t)b * Dd * Nn + (size_t)d * Nn + n0);
        const float4* trow = (const float4*)&Esm[d * 64];
#pragma unroll
        for (int qq = 0; qq < 4; ++qq) orow[seg * 4 + qq] = trow[seg * 4 + qq];
    }
    int blk = b * gridDim.x + blockIdx.x;
    if (tid < 64) {
        float s = 0.f;
#pragma unroll
        for (int t = 0; t < 16; ++t) s += Wsm[t * 64 + tid];
        g_partial[blk * 128 + tid] = s;
    }
    __syncthreads();
#pragma unroll
    for (int j = 0; j < 4; ++j) Wsm[ty * 64 + tx * 4 + j] = psq[j];
    __syncthreads();
    if (tid < 64) {
        float s = 0.f;
#pragma unroll
        for (int t = 0; t < 16; ++t) s += Wsm[t * 64 + tid];
        g_partial[blk * 128 + 64 + tid] = s;
    }
}

// ---------------- finalize BN stats (deterministic) -------------------------
__global__ void finalize_kernel(const float* __restrict__ gamma, const float* __restrict__ beta) {
    int d = threadIdx.x;  // 64 threads
    float s = 0.f, s2 = 0.f;
    const int nblk = Bb * Nn / 64;
#pragma unroll 8
    for (int blk = 0; blk < nblk; ++blk) {
        s += g_partial[blk * 128 + d];
        s2 += g_partial[blk * 128 + 64 + d];
    }
    const float inv = 1.0f / (float)(Bb * Nn);
    float mean = s * inv;
    float var = s2 * inv - mean * mean;
    float sc = gamma[d] * rsqrtf(var + 1e-5f);
    g_scale[d] = sc;
    g_shift[d] = beta[d] - mean * sc;
}

// ---------------- apply BN in place on d_out --------------------------------
__global__ void bn_apply(float* __restrict__ out) {
    int i = blockIdx.x * 256 + threadIdx.x;
    float4 v = ((float4*)out)[i];
    int d = (i >> 11) & 63;
    float sc = g_scale[d], sh = g_shift[d];
    v.x = fmaf(v.x, sc, sh);
    v.y = fmaf(v.y, sc, sh);
    v.z = fmaf(v.z, sc, sh);
    v.w = fmaf(v.w, sc, sh);
    ((float4*)out)[i] = v;
}

// ---------------- launch ----------------------------------------------------
extern "C" void kernel_launch(void* const* d_in, const int* in_sizes, int n_in,
                              void* d_out, int out_size) {
    const float* x = (const float*)d_in[0];
    const float* pos = (const float*)d_in[1];
    const float* filt = (const float*)d_in[2];
    const float* gamma = (const float*)d_in[3];
    const float* beta = (const float*)d_in[4];
    float* out = (float*)d_out;

    prep_sq<<<dim3(Nn / 256, Bb), 256>>>(pos);
    prep_xT<<<dim3(Nn / 32, Cc / 32, Bb), dim3(32, 8)>>>(x);
    prep_wsum<<<(Cc * Dd) / 256, 256>>>(filt);
    knn_partial<<<dim3(Nn / 128, S_CHUNK, Bb), 128>>>(pos);
    knn_merge<<<(Bb * Nn) / 128, 128>>>();
    gconv_kernel<<<dim3(Nn / 64, Bb), 256>>>(filt, out);
    finalize_kernel<<<1, 64>>>(gamma, beta);
    bn_apply<<<(Bb * Dd * Nn / 4) / 256, 256>>>(out);
}